// round 7
// baseline (speedup 1.0000x reference)
#include <cuda_runtime.h>
#include <math.h>
#include <stdint.h>

#define B_   64
#define NV   40000
#define P_   100
#define NJ   24
#define SKEL_OFF 7680000   // 64*40000*3

// ---------------- scratch (device globals; no allocation allowed) ----------------
__device__ float g_G1[B_ * NJ * 12];
__device__ float g_part[23 * 4 * B_ * 6];
__device__ float g_spart[30 * 8 * B_ * 6];
__device__ float g_vp[30 * 128 * B_ * 3];   // gathered v_posed: [row*128+vert][b][3]

// ---------------- cp.async helpers ----------------
__device__ __forceinline__ void cp16(uint32_t dst, const void* src) {
    asm volatile("cp.async.cg.shared.global [%0], [%1], 16;" :: "r"(dst), "l"(src));
}
__device__ __forceinline__ void cp_commit() {
    asm volatile("cp.async.commit_group;");
}
template <int N>
__device__ __forceinline__ void cp_wait() {
    asm volatile("cp.async.wait_group %0;" :: "n"(N));
}

// ---------------- Kernel A1: gathered v_posed (30 rows) + min/max (23 rows) -----
// grid (30 rows, 4 chunks), block (32 idx-lanes, 8 batch-groups) = 256 threads
__global__ __launch_bounds__(256) void k_joint_gather(
    const float* __restrict__ beta, const float* __restrict__ sd,
    const float* __restrict__ vt, const int* __restrict__ joint_idx,
    const int* __restrict__ add_idx)
{
    extern __shared__ float sm[];
    float* beta_s = sm;          // [64][100]
    float* sd_cs  = sm + 6400;   // [100][96]
    __shared__ int idxs[32];

    int row = blockIdx.x, ch = blockIdx.y;
    int tid = threadIdx.y * 32 + threadIdx.x;
    const int* src = (row < 23) ? (joint_idx + row * 128) : (add_idx + (row - 23) * 128);

    if (tid < 32) idxs[tid] = src[ch * 32 + tid];
    for (int i = tid; i < 6400; i += 256) beta_s[i] = beta[i];
    __syncthreads();

    for (int i = tid; i < 3200; i += 256) {
        int p = i >> 5, s = i & 31;
        size_t base = (size_t)p * 120000 + 3 * idxs[s];
        sd_cs[p * 96 + s * 3 + 0] = sd[base + 0];
        sd_cs[p * 96 + s * 3 + 1] = sd[base + 1];
        sd_cs[p * 96 + s * 3 + 2] = sd[base + 2];
    }
    __syncthreads();

    int lane = threadIdx.x, y = threadIdx.y;
    float acc[24];
    #pragma unroll
    for (int t = 0; t < 24; t++) acc[t] = 0.f;

    for (int p = 0; p < 100; p++) {
        float s0 = sd_cs[p * 96 + lane * 3 + 0];
        float s1 = sd_cs[p * 96 + lane * 3 + 1];
        float s2 = sd_cs[p * 96 + lane * 3 + 2];
        #pragma unroll
        for (int bb = 0; bb < 8; bb++) {
            float bp = beta_s[(y * 8 + bb) * 100 + p];
            acc[bb * 3 + 0] = fmaf(bp, s0, acc[bb * 3 + 0]);
            acc[bb * 3 + 1] = fmaf(bp, s1, acc[bb * 3 + 1]);
            acc[bb * 3 + 2] = fmaf(bp, s2, acc[bb * 3 + 2]);
        }
    }
    int myidx = idxs[lane];
    float v0 = vt[3 * myidx + 0], v1 = vt[3 * myidx + 1], v2 = vt[3 * myidx + 2];
    #pragma unroll
    for (int bb = 0; bb < 8; bb++) {
        acc[bb * 3 + 0] += v0; acc[bb * 3 + 1] += v1; acc[bb * 3 + 2] += v2;
    }

    // persist gathered v_posed: thread's 24 floats are contiguous in g_vp
    {
        float4* dst = (float4*)(g_vp + ((size_t)(row * 128 + ch * 32 + lane) * 64 + y * 8) * 3);
        dst[0] = make_float4(acc[0],  acc[1],  acc[2],  acc[3]);
        dst[1] = make_float4(acc[4],  acc[5],  acc[6],  acc[7]);
        dst[2] = make_float4(acc[8],  acc[9],  acc[10], acc[11]);
        dst[3] = make_float4(acc[12], acc[13], acc[14], acc[15]);
        dst[4] = make_float4(acc[16], acc[17], acc[18], acc[19]);
        dst[5] = make_float4(acc[20], acc[21], acc[22], acc[23]);
    }

    if (row < 23) {
        float mx[24];
        #pragma unroll
        for (int t = 0; t < 24; t++) mx[t] = acc[t];
        for (int off = 16; off; off >>= 1) {
            #pragma unroll
            for (int t = 0; t < 24; t++) {
                float om = __shfl_xor_sync(0xffffffffu, acc[t], off);
                float ox = __shfl_xor_sync(0xffffffffu, mx[t],  off);
                acc[t] = fminf(acc[t], om);
                mx[t]  = fmaxf(mx[t],  ox);
            }
        }
        if (lane < 8) {
            int b = y * 8 + lane;
            float* dst = g_part + ((size_t)(row * 4 + ch) * 64 + b) * 6;
            dst[0] = acc[lane * 3 + 0]; dst[1] = acc[lane * 3 + 1]; dst[2] = acc[lane * 3 + 2];
            dst[3] = mx[lane * 3 + 0];  dst[4] = mx[lane * 3 + 1];  dst[5] = mx[lane * 3 + 2];
        }
    }
}

// ---------------- Kernel A2: chunk-reduce + Rodrigues + kinematic chain -> G1 ----
__global__ void k_chain(const float* __restrict__ pose)
{
    int b = blockIdx.x, t = threadIdx.x;
    __shared__ float R[24][9], Jl[24][3], Gr[24][9], Gt[24][3];

    if (t < 24) {
        if (t == 0) {
            Jl[0][0] = 0.f; Jl[0][1] = 0.f; Jl[0][2] = 0.f;
        } else {
            int j = t - 1;
            float mn0 = 3.4e38f, mn1 = 3.4e38f, mn2 = 3.4e38f;
            float mx0 = -3.4e38f, mx1 = -3.4e38f, mx2 = -3.4e38f;
            #pragma unroll
            for (int ch = 0; ch < 4; ch++) {
                const float* s = g_part + ((size_t)(j * 4 + ch) * 64 + b) * 6;
                mn0 = fminf(mn0, s[0]); mn1 = fminf(mn1, s[1]); mn2 = fminf(mn2, s[2]);
                mx0 = fmaxf(mx0, s[3]); mx1 = fmaxf(mx1, s[4]); mx2 = fmaxf(mx2, s[5]);
            }
            Jl[t][0] = 0.5f * (mn0 + mx0);
            Jl[t][1] = 0.5f * (mn1 + mx1);
            Jl[t][2] = 0.5f * (mn2 + mx2);
        }

        float rx = pose[b * 72 + t * 3 + 0];
        float ry = pose[b * 72 + t * 3 + 1];
        float rz = pose[b * 72 + t * 3 + 2];
        float th = sqrtf(rx * rx + ry * ry + rz * rz);
        th = fmaxf(th, 1e-6f);
        float s, c;
        sincosf(th, &s, &c);
        float inv = 1.0f / th;
        float x = rx * inv, y = ry * inv, z = rz * inv;
        float omc = 1.0f - c;
        R[t][0] = c + omc * x * x;     R[t][1] = omc * x * y - s * z; R[t][2] = omc * x * z + s * y;
        R[t][3] = omc * x * y + s * z; R[t][4] = c + omc * y * y;     R[t][5] = omc * y * z - s * x;
        R[t][6] = omc * x * z - s * y; R[t][7] = omc * y * z + s * x; R[t][8] = c + omc * z * z;
    }
    __syncthreads();

    if (t == 0) {
        for (int q = 0; q < 9; q++) Gr[0][q] = R[0][q];
        Gt[0][0] = Jl[0][0]; Gt[0][1] = Jl[0][1]; Gt[0][2] = Jl[0][2];
        for (int i = 1; i < 24; i++) {
            int p = (i - 1) >> 1;
            for (int r = 0; r < 3; r++)
                for (int cc = 0; cc < 3; cc++)
                    Gr[i][r * 3 + cc] = Gr[p][r * 3 + 0] * R[i][0 + cc]
                                      + Gr[p][r * 3 + 1] * R[i][3 + cc]
                                      + Gr[p][r * 3 + 2] * R[i][6 + cc];
            float dx = Jl[i][0] - Jl[p][0];
            float dy = Jl[i][1] - Jl[p][1];
            float dz = Jl[i][2] - Jl[p][2];
            for (int r = 0; r < 3; r++)
                Gt[i][r] = Gr[p][r * 3 + 0] * dx + Gr[p][r * 3 + 1] * dy
                         + Gr[p][r * 3 + 2] * dz + Gt[p][r];
        }
    }
    __syncthreads();

    if (t < 24) {
        float* d = g_G1 + ((size_t)b * 24 + t) * 12;
        for (int r = 0; r < 3; r++) {
            float tc = Gr[t][r * 3 + 0] * Jl[t][0] + Gr[t][r * 3 + 1] * Jl[t][1]
                     + Gr[t][r * 3 + 2] * Jl[t][2];
            d[r * 4 + 0] = Gr[t][r * 3 + 0];
            d[r * 4 + 1] = Gr[t][r * 3 + 1];
            d[r * 4 + 2] = Gr[t][r * 3 + 2];
            d[r * 4 + 3] = Gt[t][r] - tc;
        }
    }
}

// ---------------- Kernel B: fused shape blend + skinning (cp.async pipelined) ---
// grid (1250, 2), block (32, 8) = 256 threads, 4 vertices/thread
// smem (floats): g1 float4[72][pitch 33] | w[768] | beta[100][33] | sd double [2][2400]
#define PC 25
#define SM_G1    0
#define SM_W     (72 * 33 * 4)                   // 9504
#define SM_BETA  (SM_W + 24 * 32)                // 10272
#define SM_SD    ((SM_BETA + 100 * 33 + 3) & ~3) // 13572 (16B aligned)
#define SM_TOT   (SM_SD + 2 * PC * 96)           // 18372 floats = 73488 B

__global__ __launch_bounds__(256, 3) void k_main(
    const float* __restrict__ beta, const float* __restrict__ trans,
    const float* __restrict__ sd, const float* __restrict__ vt,
    const float* __restrict__ wts, float* __restrict__ out)
{
    extern __shared__ float sm[];
    float4* g1_s4 = (float4*)(sm + SM_G1);   // [j=3k+r][b], pitch 33
    float* w_s    = sm + SM_W;
    float* beta_s = sm + SM_BETA;

    int tid = threadIdx.y * 32 + threadIdx.x;
    int n0 = blockIdx.x * 32;
    int b0 = blockIdx.y * 32;

    uint32_t sd_sm_u32 = (uint32_t)__cvta_generic_to_shared(sm + SM_SD);
    const float* sd_blk = sd + 3 * n0;

    // prefetch sd chunk 0 into buffer 0
    {
        const float* base = sd_blk;
        for (int i = tid; i < 600; i += 256) {
            int p = i / 24, q = i - p * 24;
            cp16(sd_sm_u32 + (uint32_t)i * 16, base + (size_t)p * 120000 + q * 4);
        }
        cp_commit();
    }

    // one-time stages: G1 transpose (coalesced LDG -> strided STS, conflict-free reads later)
    for (int i = tid; i < 2304; i += 256) {
        int bb = i / 72, j = i - bb * 72;
        float4 v = ((const float4*)g_G1)[(size_t)(b0 + bb) * 72 + j];
        g1_s4[j * 33 + bb] = v;
    }
    for (int i = tid; i < 768; i += 256) {
        int k = i >> 5, vl = i & 31;
        w_s[k * 32 + vl] = wts[(size_t)(n0 + vl) * 24 + k];
    }
    for (int i = tid; i < 3200; i += 256) {
        int p = i >> 5, bb = i & 31;
        beta_s[p * 33 + bb] = beta[(b0 + bb) * 100 + p];
    }

    int b = threadIdx.x, vl0 = threadIdx.y * 4;

    float acc[12];
    {
        const float4* v4 = (const float4*)(vt + (size_t)(n0 + vl0) * 3);
        float4 a = v4[0], b4 = v4[1], c4 = v4[2];
        acc[0] = a.x; acc[1] = a.y; acc[2] = a.z; acc[3] = a.w;
        acc[4] = b4.x; acc[5] = b4.y; acc[6] = b4.z; acc[7] = b4.w;
        acc[8] = c4.x; acc[9] = c4.y; acc[10] = c4.z; acc[11] = c4.w;
    }

    // pipelined shape blend over 4 chunks of PC=25
    #pragma unroll
    for (int c = 0; c < 4; c++) {
        if (c < 3) {
            const float* base = sd_blk + (size_t)((c + 1) * PC) * 120000;
            uint32_t dstb = sd_sm_u32 + (uint32_t)(((c + 1) & 1) * 600) * 16;
            for (int i = tid; i < 600; i += 256) {
                int p = i / 24, q = i - p * 24;
                cp16(dstb + (uint32_t)i * 16, base + (size_t)p * 120000 + q * 4);
            }
            cp_commit();
            cp_wait<1>();
        } else {
            cp_wait<0>();
        }
        __syncthreads();

        const float4* sdp = ((const float4*)(sm + SM_SD)) + (c & 1) * 600 + threadIdx.y * 3;
        const float* bcol = beta_s + c * PC * 33 + b;
        #pragma unroll 5
        for (int p = 0; p < PC; p++) {
            float bp = bcol[p * 33];
            float4 s0 = sdp[p * 24 + 0];
            float4 s1 = sdp[p * 24 + 1];
            float4 s2 = sdp[p * 24 + 2];
            acc[0]  = fmaf(bp, s0.x, acc[0]);
            acc[1]  = fmaf(bp, s0.y, acc[1]);
            acc[2]  = fmaf(bp, s0.z, acc[2]);
            acc[3]  = fmaf(bp, s0.w, acc[3]);
            acc[4]  = fmaf(bp, s1.x, acc[4]);
            acc[5]  = fmaf(bp, s1.y, acc[5]);
            acc[6]  = fmaf(bp, s1.z, acc[6]);
            acc[7]  = fmaf(bp, s1.w, acc[7]);
            acc[8]  = fmaf(bp, s2.x, acc[8]);
            acc[9]  = fmaf(bp, s2.y, acc[9]);
            acc[10] = fmaf(bp, s2.z, acc[10]);
            acc[11] = fmaf(bp, s2.w, acc[11]);
        }
        __syncthreads();
    }

    float tr0 = trans[(b0 + b) * 3 + 0];
    float tr1 = trans[(b0 + b) * 3 + 1];
    float tr2 = trans[(b0 + b) * 3 + 2];
    float o[12] = {tr0, tr1, tr2, tr0, tr1, tr2, tr0, tr1, tr2, tr0, tr1, tr2};

    #pragma unroll 4
    for (int k = 0; k < 24; k++) {
        float4 g0  = g1_s4[(k * 3 + 0) * 33 + b];
        float4 g1v = g1_s4[(k * 3 + 1) * 33 + b];
        float4 g2  = g1_s4[(k * 3 + 2) * 33 + b];
        float4 w4 = *(const float4*)(w_s + k * 32 + vl0);
        float wv[4] = {w4.x, w4.y, w4.z, w4.w};
        #pragma unroll
        for (int vi = 0; vi < 4; vi++) {
            float vx = acc[vi * 3 + 0], vy = acc[vi * 3 + 1], vz = acc[vi * 3 + 2];
            float t0 = fmaf(g0.x,  vx, fmaf(g0.y,  vy, fmaf(g0.z,  vz, g0.w)));
            float t1 = fmaf(g1v.x, vx, fmaf(g1v.y, vy, fmaf(g1v.z, vz, g1v.w)));
            float t2 = fmaf(g2.x,  vx, fmaf(g2.y,  vy, fmaf(g2.z,  vz, g2.w)));
            o[vi * 3 + 0] = fmaf(wv[vi], t0, o[vi * 3 + 0]);
            o[vi * 3 + 1] = fmaf(wv[vi], t1, o[vi * 3 + 1]);
            o[vi * 3 + 2] = fmaf(wv[vi], t2, o[vi * 3 + 2]);
        }
    }

    float4* dst = (float4*)(out + ((size_t)(b0 + b) * 40000 + n0 + vl0) * 3);
    dst[0] = make_float4(o[0], o[1], o[2],  o[3]);
    dst[1] = make_float4(o[4], o[5], o[6],  o[7]);
    dst[2] = make_float4(o[8], o[9], o[10], o[11]);
}

// ---------------- Kernel C1: skeleton from g_vp (no dependence on out) ----------
// grid (30 rows, 8 chunks of 16 verts), block (64 batches, 4) = 256 threads
#define SK_G1  0                         // float4[72][pitch 65] = 4680 f4 = 18720 f
#define SK_W   (72 * 65 * 4)             // 18720 ; [16][24] = 384
#define SK_VP  (SK_W + 384)              // 19104 ; [16][64][3] = 3072
#define SK_TR  (SK_VP + 3072)            // 22176 ; [64][3] = 192
#define SK_TOT (SK_TR + 192)             // 22368 floats = 89472 B

__global__ __launch_bounds__(256) void k_skel2(
    const float* __restrict__ wts, const float* __restrict__ trans,
    const int* __restrict__ joint_idx, const int* __restrict__ add_idx)
{
    extern __shared__ float sm[];
    float4* g1_s4 = (float4*)(sm + SK_G1);
    float* w_s  = sm + SK_W;
    float* vp_s = sm + SK_VP;
    float* tr_s = sm + SK_TR;
    __shared__ int vid[16];
    __shared__ float red[4][64][6];

    int row = blockIdx.x, ch = blockIdx.y;
    int tid = threadIdx.y * 64 + threadIdx.x;
    const int* src = (row < 23) ? (joint_idx + row * 128) : (add_idx + (row - 23) * 128);

    if (tid < 16) vid[tid] = src[ch * 16 + tid];
    __syncthreads();

    // stage G1 all 64 batches: coalesced LDG -> pitch-65 transpose
    for (int i = tid; i < 4608; i += 256) {
        int bb = i / 72, j = i - bb * 72;
        g1_s4[j * 65 + bb] = ((const float4*)g_G1)[(size_t)bb * 72 + j];
    }
    // weights for the 16 verts
    for (int i = tid; i < 384; i += 256) {
        int v = i / 24, k = i - v * 24;
        w_s[i] = wts[(size_t)vid[v] * 24 + k];
    }
    // gathered v_posed: contiguous block of 3072 floats
    {
        const float4* srcv = (const float4*)(g_vp + (size_t)(row * 128 + ch * 16) * 192);
        float4* dstv = (float4*)vp_s;
        for (int i = tid; i < 768; i += 256) dstv[i] = srcv[i];
    }
    for (int i = tid; i < 192; i += 256) tr_s[i] = trans[i];
    __syncthreads();

    int b = threadIdx.x, q = threadIdx.y;
    float mn0 = 3.4e38f, mn1 = 3.4e38f, mn2 = 3.4e38f;
    float mx0 = -3.4e38f, mx1 = -3.4e38f, mx2 = -3.4e38f;
    float t0b = tr_s[b * 3 + 0], t1b = tr_s[b * 3 + 1], t2b = tr_s[b * 3 + 2];

    #pragma unroll
    for (int vi = 0; vi < 4; vi++) {
        int v = q * 4 + vi;
        float x = vp_s[(v * 64 + b) * 3 + 0];
        float y = vp_s[(v * 64 + b) * 3 + 1];
        float z = vp_s[(v * 64 + b) * 3 + 2];
        float o0 = t0b, o1 = t1b, o2 = t2b;
        #pragma unroll 4
        for (int k = 0; k < 24; k++) {
            float wv = w_s[v * 24 + k];
            float4 g0  = g1_s4[(k * 3 + 0) * 65 + b];
            float4 g1v = g1_s4[(k * 3 + 1) * 65 + b];
            float4 g2  = g1_s4[(k * 3 + 2) * 65 + b];
            float p0 = fmaf(g0.x,  x, fmaf(g0.y,  y, fmaf(g0.z,  z, g0.w)));
            float p1 = fmaf(g1v.x, x, fmaf(g1v.y, y, fmaf(g1v.z, z, g1v.w)));
            float p2 = fmaf(g2.x,  x, fmaf(g2.y,  y, fmaf(g2.z,  z, g2.w)));
            o0 = fmaf(wv, p0, o0);
            o1 = fmaf(wv, p1, o1);
            o2 = fmaf(wv, p2, o2);
        }
        mn0 = fminf(mn0, o0); mx0 = fmaxf(mx0, o0);
        mn1 = fminf(mn1, o1); mx1 = fmaxf(mx1, o1);
        mn2 = fminf(mn2, o2); mx2 = fmaxf(mx2, o2);
    }

    red[q][b][0] = mn0; red[q][b][1] = mn1; red[q][b][2] = mn2;
    red[q][b][3] = mx0; red[q][b][4] = mx1; red[q][b][5] = mx2;
    __syncthreads();
    if (q == 0) {
        #pragma unroll
        for (int c = 1; c < 4; c++) {
            mn0 = fminf(mn0, red[c][b][0]); mn1 = fminf(mn1, red[c][b][1]); mn2 = fminf(mn2, red[c][b][2]);
            mx0 = fmaxf(mx0, red[c][b][3]); mx1 = fmaxf(mx1, red[c][b][4]); mx2 = fmaxf(mx2, red[c][b][5]);
        }
        float* dst = g_spart + ((size_t)(row * 8 + ch) * 64 + b) * 6;
        dst[0] = mn0; dst[1] = mn1; dst[2] = mn2;
        dst[3] = mx0; dst[4] = mx1; dst[5] = mx2;
    }
}

// ---------------- Kernel C2: combine skeleton partials ----------------
__global__ void k_skel_comb(float* __restrict__ out)
{
    int j = blockIdx.x, b = threadIdx.x;
    int orow = (j < 23) ? (1 + j) : (24 + (j - 23));
    float mn0 = 3.4e38f, mn1 = 3.4e38f, mn2 = 3.4e38f;
    float mx0 = -3.4e38f, mx1 = -3.4e38f, mx2 = -3.4e38f;
    #pragma unroll
    for (int ch = 0; ch < 8; ch++) {
        const float* s = g_spart + ((size_t)(j * 8 + ch) * 64 + b) * 6;
        mn0 = fminf(mn0, s[0]); mn1 = fminf(mn1, s[1]); mn2 = fminf(mn2, s[2]);
        mx0 = fmaxf(mx0, s[3]); mx1 = fmaxf(mx1, s[4]); mx2 = fmaxf(mx2, s[5]);
    }
    float* s = out + SKEL_OFF + ((size_t)b * 31 + orow) * 3;
    s[0] = 0.5f * (mn0 + mx0);
    s[1] = 0.5f * (mn1 + mx1);
    s[2] = 0.5f * (mn2 + mx2);
    if (j == 0) {
        float* z0 = out + SKEL_OFF + (size_t)b * 31 * 3;
        z0[0] = 0.f; z0[1] = 0.f; z0[2] = 0.f;
    }
}

// ---------------- launch ----------------
extern "C" void kernel_launch(void* const* d_in, const int* in_sizes, int n_in,
                              void* d_out, int out_size)
{
    const float* beta      = (const float*)d_in[0];
    const float* pose      = (const float*)d_in[1];
    const float* trans     = (const float*)d_in[2];
    const float* sd        = (const float*)d_in[3];
    const float* vt        = (const float*)d_in[4];
    const float* wts       = (const float*)d_in[5];
    const int*   joint_idx = (const int*)d_in[8];
    const int*   add_idx   = (const int*)d_in[9];
    float* out = (float*)d_out;

    cudaFuncSetAttribute(k_joint_gather, cudaFuncAttributeMaxDynamicSharedMemorySize, 64000);
    cudaFuncSetAttribute(k_main,         cudaFuncAttributeMaxDynamicSharedMemorySize, SM_TOT * 4);
    cudaFuncSetAttribute(k_skel2,        cudaFuncAttributeMaxDynamicSharedMemorySize, SK_TOT * 4);

    k_joint_gather<<<dim3(30, 4), dim3(32, 8), 64000>>>(beta, sd, vt, joint_idx, add_idx);
    k_chain<<<64, 32>>>(pose);
    k_skel2<<<dim3(30, 8), dim3(64, 4), SK_TOT * 4>>>(wts, trans, joint_idx, add_idx);
    k_skel_comb<<<30, 64>>>(out);
    k_main<<<dim3(1250, 2), dim3(32, 8), SM_TOT * 4>>>(beta, trans, sd, vt, wts, out);
}

// round 8
// speedup vs baseline: 1.0235x; 1.0235x over previous
#include <cuda_runtime.h>
#include <math.h>
#include <stdint.h>

#define B_   64
#define NV   40000
#define P_   100
#define NJ   24
#define SKEL_OFF 7680000   // 64*40000*3

typedef unsigned long long u64;

// ---------------- scratch (device globals; no allocation allowed) ----------------
__device__ float g_G1[B_ * NJ * 12];
__device__ float g_part[23 * 4 * B_ * 6];
__device__ float g_spart[30 * 8 * B_ * 6];

// ---------------- f32x2 helpers ----------------
__device__ __forceinline__ u64 pk2(float lo, float hi) {
    u64 r; asm("mov.b64 %0,{%1,%2};" : "=l"(r) : "f"(lo), "f"(hi)); return r;
}
__device__ __forceinline__ void up2(u64 v, float& lo, float& hi) {
    asm("mov.b64 {%0,%1},%2;" : "=f"(lo), "=f"(hi) : "l"(v));
}
__device__ __forceinline__ u64 ffma2(u64 a, u64 b, u64 c) {
    u64 d; asm("fma.rn.f32x2 %0,%1,%2,%3;" : "=l"(d) : "l"(a), "l"(b), "l"(c)); return d;
}

// ---------------- cp.async helpers ----------------
__device__ __forceinline__ void cp16(uint32_t dst, const void* src) {
    asm volatile("cp.async.cg.shared.global [%0], [%1], 16;" :: "r"(dst), "l"(src));
}
__device__ __forceinline__ void cp_commit() {
    asm volatile("cp.async.commit_group;");
}
template <int N>
__device__ __forceinline__ void cp_wait() {
    asm volatile("cp.async.wait_group %0;" :: "n"(N));
}

// ---------------- Kernel A1: gathered v_posed + per-chunk min/max ----------------
// grid (23, 4), block (32, 8)
__global__ __launch_bounds__(256) void k_joint_gather(
    const float* __restrict__ beta, const float* __restrict__ sd,
    const float* __restrict__ vt, const int* __restrict__ joint_idx)
{
    extern __shared__ float sm[];
    float* beta_s = sm;          // [64][100]
    float* sd_cs  = sm + 6400;   // [100][96]
    __shared__ int idxs[32];

    int j = blockIdx.x, ch = blockIdx.y;
    int tid = threadIdx.y * 32 + threadIdx.x;

    if (tid < 32) idxs[tid] = joint_idx[j * 128 + ch * 32 + tid];
    for (int i = tid; i < 6400; i += 256) beta_s[i] = beta[i];
    __syncthreads();

    for (int i = tid; i < 3200; i += 256) {
        int p = i >> 5, s = i & 31;
        size_t base = (size_t)p * 120000 + 3 * idxs[s];
        sd_cs[p * 96 + s * 3 + 0] = sd[base + 0];
        sd_cs[p * 96 + s * 3 + 1] = sd[base + 1];
        sd_cs[p * 96 + s * 3 + 2] = sd[base + 2];
    }
    __syncthreads();

    int lane = threadIdx.x, y = threadIdx.y;
    float acc[24];
    #pragma unroll
    for (int t = 0; t < 24; t++) acc[t] = 0.f;

    for (int p = 0; p < 100; p++) {
        float s0 = sd_cs[p * 96 + lane * 3 + 0];
        float s1 = sd_cs[p * 96 + lane * 3 + 1];
        float s2 = sd_cs[p * 96 + lane * 3 + 2];
        #pragma unroll
        for (int bb = 0; bb < 8; bb++) {
            float bp = beta_s[(y * 8 + bb) * 100 + p];
            acc[bb * 3 + 0] = fmaf(bp, s0, acc[bb * 3 + 0]);
            acc[bb * 3 + 1] = fmaf(bp, s1, acc[bb * 3 + 1]);
            acc[bb * 3 + 2] = fmaf(bp, s2, acc[bb * 3 + 2]);
        }
    }
    int myidx = idxs[lane];
    float v0 = vt[3 * myidx + 0], v1 = vt[3 * myidx + 1], v2 = vt[3 * myidx + 2];
    #pragma unroll
    for (int bb = 0; bb < 8; bb++) {
        acc[bb * 3 + 0] += v0; acc[bb * 3 + 1] += v1; acc[bb * 3 + 2] += v2;
    }
    float mx[24];
    #pragma unroll
    for (int t = 0; t < 24; t++) mx[t] = acc[t];

    for (int off = 16; off; off >>= 1) {
        #pragma unroll
        for (int t = 0; t < 24; t++) {
            float om = __shfl_xor_sync(0xffffffffu, acc[t], off);
            float ox = __shfl_xor_sync(0xffffffffu, mx[t],  off);
            acc[t] = fminf(acc[t], om);
            mx[t]  = fmaxf(mx[t],  ox);
        }
    }
    if (lane < 8) {
        int b = y * 8 + lane;
        float* dst = g_part + ((size_t)(j * 4 + ch) * 64 + b) * 6;
        dst[0] = acc[lane * 3 + 0]; dst[1] = acc[lane * 3 + 1]; dst[2] = acc[lane * 3 + 2];
        dst[3] = mx[lane * 3 + 0];  dst[4] = mx[lane * 3 + 1];  dst[5] = mx[lane * 3 + 2];
    }
}

// ---------------- Kernel A2: chunk-reduce + Rodrigues + kinematic chain -> G1 ----
__global__ void k_chain(const float* __restrict__ pose)
{
    int b = blockIdx.x, t = threadIdx.x;
    __shared__ float R[24][9], Jl[24][3], Gr[24][9], Gt[24][3];

    if (t < 24) {
        if (t == 0) {
            Jl[0][0] = 0.f; Jl[0][1] = 0.f; Jl[0][2] = 0.f;
        } else {
            int j = t - 1;
            float mn0 = 3.4e38f, mn1 = 3.4e38f, mn2 = 3.4e38f;
            float mx0 = -3.4e38f, mx1 = -3.4e38f, mx2 = -3.4e38f;
            #pragma unroll
            for (int ch = 0; ch < 4; ch++) {
                const float* s = g_part + ((size_t)(j * 4 + ch) * 64 + b) * 6;
                mn0 = fminf(mn0, s[0]); mn1 = fminf(mn1, s[1]); mn2 = fminf(mn2, s[2]);
                mx0 = fmaxf(mx0, s[3]); mx1 = fmaxf(mx1, s[4]); mx2 = fmaxf(mx2, s[5]);
            }
            Jl[t][0] = 0.5f * (mn0 + mx0);
            Jl[t][1] = 0.5f * (mn1 + mx1);
            Jl[t][2] = 0.5f * (mn2 + mx2);
        }

        float rx = pose[b * 72 + t * 3 + 0];
        float ry = pose[b * 72 + t * 3 + 1];
        float rz = pose[b * 72 + t * 3 + 2];
        float th = sqrtf(rx * rx + ry * ry + rz * rz);
        th = fmaxf(th, 1e-6f);
        float s, c;
        sincosf(th, &s, &c);
        float inv = 1.0f / th;
        float x = rx * inv, y = ry * inv, z = rz * inv;
        float omc = 1.0f - c;
        R[t][0] = c + omc * x * x;     R[t][1] = omc * x * y - s * z; R[t][2] = omc * x * z + s * y;
        R[t][3] = omc * x * y + s * z; R[t][4] = c + omc * y * y;     R[t][5] = omc * y * z - s * x;
        R[t][6] = omc * x * z - s * y; R[t][7] = omc * y * z + s * x; R[t][8] = c + omc * z * z;
    }
    __syncthreads();

    if (t == 0) {
        for (int q = 0; q < 9; q++) Gr[0][q] = R[0][q];
        Gt[0][0] = Jl[0][0]; Gt[0][1] = Jl[0][1]; Gt[0][2] = Jl[0][2];
        for (int i = 1; i < 24; i++) {
            int p = (i - 1) >> 1;
            for (int r = 0; r < 3; r++)
                for (int cc = 0; cc < 3; cc++)
                    Gr[i][r * 3 + cc] = Gr[p][r * 3 + 0] * R[i][0 + cc]
                                      + Gr[p][r * 3 + 1] * R[i][3 + cc]
                                      + Gr[p][r * 3 + 2] * R[i][6 + cc];
            float dx = Jl[i][0] - Jl[p][0];
            float dy = Jl[i][1] - Jl[p][1];
            float dz = Jl[i][2] - Jl[p][2];
            for (int r = 0; r < 3; r++)
                Gt[i][r] = Gr[p][r * 3 + 0] * dx + Gr[p][r * 3 + 1] * dy
                         + Gr[p][r * 3 + 2] * dz + Gt[p][r];
        }
    }
    __syncthreads();

    if (t < 24) {
        float* d = g_G1 + ((size_t)b * 24 + t) * 12;
        for (int r = 0; r < 3; r++) {
            float tc = Gr[t][r * 3 + 0] * Jl[t][0] + Gr[t][r * 3 + 1] * Jl[t][1]
                     + Gr[t][r * 3 + 2] * Jl[t][2];
            d[r * 4 + 0] = Gr[t][r * 3 + 0];
            d[r * 4 + 1] = Gr[t][r * 3 + 1];
            d[r * 4 + 2] = Gr[t][r * 3 + 2];
            d[r * 4 + 3] = Gt[t][r] - tc;
        }
    }
}

// ---------------- Kernel B: fused shape blend + skinning, f32x2 packed ----------
// grid (1250, 2), block (32, 8), 4 vertices/thread
// smem (floats): g1packed float4[72][33] | w2 u64[24][32] | beta[100][33] | sd dbl [2][2400]
// g1 row layout per joint k (float4 rows, pitch 33 float4s):
//   row 3k+0 : (g0.x, g1.x, g0.y, g1.y)   -> ulonglong2 (pairX, pairY)
//   row 3k+1 : (g0.z, g1.z, g0.w, g1.w)   -> ulonglong2 (pairZ, pairW)
//   row 3k+2 : g2 (unchanged)
#define PC 25
#define SM_G1    0
#define SM_W2    (72 * 33 * 4)                   // 9504  (u64[768] = 1536 floats)
#define SM_BETA  (SM_W2 + 1536)                  // 11040
#define SM_SD    ((SM_BETA + 100 * 33 + 3) & ~3) // 14340 (16B aligned)
#define SM_TOT   (SM_SD + 2 * PC * 96)           // 19140 floats = 76560 B

__global__ __launch_bounds__(256, 3) void k_main(
    const float* __restrict__ beta, const float* __restrict__ trans,
    const float* __restrict__ sd, const float* __restrict__ vt,
    const float* __restrict__ wts, float* __restrict__ out)
{
    extern __shared__ float sm[];
    float4* g1_s4 = (float4*)(sm + SM_G1);
    u64*    w2_s  = (u64*)(sm + SM_W2);
    float*  beta_s = sm + SM_BETA;

    int tid = threadIdx.y * 32 + threadIdx.x;
    int n0 = blockIdx.x * 32;
    int b0 = blockIdx.y * 32;

    uint32_t sd_sm_u32 = (uint32_t)__cvta_generic_to_shared(sm + SM_SD);
    const float* sd_blk = sd + 3 * n0;

    // prefetch sd chunk 0
    {
        const float* base = sd_blk;
        for (int i = tid; i < 600; i += 256) {
            int p = i / 24, q = i - p * 24;
            cp16(sd_sm_u32 + (uint32_t)i * 16, base + (size_t)p * 120000 + q * 4);
        }
        cp_commit();
    }

    // stage G1 packed-transposed
    for (int i = tid; i < 2304; i += 256) {
        int bb = i / 72, j = i - bb * 72;
        int k = j / 3, r = j - k * 3;
        const float4* src = (const float4*)g_G1 + (size_t)(b0 + bb) * 72 + k * 3;
        float4 v;
        if (r == 0) {
            float4 f0 = src[0], f1 = src[1];
            v = make_float4(f0.x, f1.x, f0.y, f1.y);
        } else if (r == 1) {
            float4 f0 = src[0], f1 = src[1];
            v = make_float4(f0.z, f1.z, f0.w, f1.w);
        } else {
            v = src[2];
        }
        g1_s4[j * 33 + bb] = v;
    }
    // stage duplicated weights
    for (int i = tid; i < 768; i += 256) {
        int k = i >> 5, vl = i & 31;
        float w = wts[(size_t)(n0 + vl) * 24 + k];
        w2_s[k * 32 + vl] = pk2(w, w);
    }
    // stage beta transpose
    for (int i = tid; i < 3200; i += 256) {
        int p = i >> 5, bb = i & 31;
        beta_s[p * 33 + bb] = beta[(b0 + bb) * 100 + p];
    }

    int b = threadIdx.x, vl0 = threadIdx.y * 4;

    // packed accumulators: 6 pairs = 12 floats (vertex-major xyz stream)
    u64 a[6];
    {
        const ulonglong2* v2 = (const ulonglong2*)(vt + (size_t)(n0 + vl0) * 3);
        ulonglong2 q0 = v2[0], q1 = v2[1], q2 = v2[2];
        a[0] = q0.x; a[1] = q0.y; a[2] = q1.x; a[3] = q1.y; a[4] = q2.x; a[5] = q2.y;
    }

    // pipelined shape blend over 4 chunks of PC=25, f32x2
    #pragma unroll
    for (int c = 0; c < 4; c++) {
        if (c < 3) {
            const float* base = sd_blk + (size_t)((c + 1) * PC) * 120000;
            uint32_t dstb = sd_sm_u32 + (uint32_t)(((c + 1) & 1) * 600) * 16;
            for (int i = tid; i < 600; i += 256) {
                int p = i / 24, q = i - p * 24;
                cp16(dstb + (uint32_t)i * 16, base + (size_t)p * 120000 + q * 4);
            }
            cp_commit();
            cp_wait<1>();
        } else {
            cp_wait<0>();
        }
        __syncthreads();

        const ulonglong2* sdp = ((const ulonglong2*)(sm + SM_SD)) + (c & 1) * 600 + threadIdx.y * 3;
        const float* bcol = beta_s + c * PC * 33 + b;
        #pragma unroll 5
        for (int p = 0; p < PC; p++) {
            float bp = bcol[p * 33];
            u64 bp2 = pk2(bp, bp);
            ulonglong2 q0 = sdp[p * 24 + 0];
            ulonglong2 q1 = sdp[p * 24 + 1];
            ulonglong2 q2 = sdp[p * 24 + 2];
            a[0] = ffma2(bp2, q0.x, a[0]);
            a[1] = ffma2(bp2, q0.y, a[1]);
            a[2] = ffma2(bp2, q1.x, a[2]);
            a[3] = ffma2(bp2, q1.y, a[3]);
            a[4] = ffma2(bp2, q2.x, a[4]);
            a[5] = ffma2(bp2, q2.y, a[5]);
        }
        __syncthreads();
    }

    // unpack v_posed scalars and build duplicated pairs
    float v[12];
    up2(a[0], v[0], v[1]);  up2(a[1], v[2], v[3]);
    up2(a[2], v[4], v[5]);  up2(a[3], v[6], v[7]);
    up2(a[4], v[8], v[9]);  up2(a[5], v[10], v[11]);
    u64 vx2[4], vy2[4], vz2[4];
    #pragma unroll
    for (int vi = 0; vi < 4; vi++) {
        vx2[vi] = pk2(v[vi * 3 + 0], v[vi * 3 + 0]);
        vy2[vi] = pk2(v[vi * 3 + 1], v[vi * 3 + 1]);
        vz2[vi] = pk2(v[vi * 3 + 2], v[vi * 3 + 2]);
    }

    float tr0 = trans[(b0 + b) * 3 + 0];
    float tr1 = trans[(b0 + b) * 3 + 1];
    float tr2 = trans[(b0 + b) * 3 + 2];
    u64 o01[4];
    float o2[4];
    #pragma unroll
    for (int vi = 0; vi < 4; vi++) { o01[vi] = pk2(tr0, tr1); o2[vi] = tr2; }

    const ulonglong2* g1p = (const ulonglong2*)g1_s4;
    const ulonglong2* w2p = (const ulonglong2*)w2_s;

    #pragma unroll 4
    for (int k = 0; k < 24; k++) {
        ulonglong2 A  = g1p[(k * 3 + 0) * 33 + b];   // (pairX, pairY)
        ulonglong2 Bv = g1p[(k * 3 + 1) * 33 + b];   // (pairZ, pairW)
        float4 g2 = g1_s4[(k * 3 + 2) * 33 + b];
        ulonglong2 wA = w2p[k * 16 + (vl0 >> 1)];
        ulonglong2 wB = w2p[k * 16 + (vl0 >> 1) + 1];
        u64 wk[4] = {wA.x, wA.y, wB.x, wB.y};
        #pragma unroll
        for (int vi = 0; vi < 4; vi++) {
            u64 t = ffma2(A.x, vx2[vi], ffma2(A.y, vy2[vi], ffma2(Bv.x, vz2[vi], Bv.y)));
            o01[vi] = ffma2(wk[vi], t, o01[vi]);
            float t2 = fmaf(g2.x, v[vi * 3 + 0], fmaf(g2.y, v[vi * 3 + 1], fmaf(g2.z, v[vi * 3 + 2], g2.w)));
            float wlo = __uint_as_float((unsigned int)wk[vi]);
            o2[vi] = fmaf(wlo, t2, o2[vi]);
        }
    }

    float oo[8];
    up2(o01[0], oo[0], oo[1]); up2(o01[1], oo[2], oo[3]);
    up2(o01[2], oo[4], oo[5]); up2(o01[3], oo[6], oo[7]);

    float4* dst = (float4*)(out + ((size_t)(b0 + b) * 40000 + n0 + vl0) * 3);
    dst[0] = make_float4(oo[0], oo[1], o2[0], oo[2]);
    dst[1] = make_float4(oo[3], o2[1], oo[4], oo[5]);
    dst[2] = make_float4(o2[2], oo[6], oo[7], o2[3]);
}

// ---------------- Kernel C1: skeleton partials (reads out) ----------------
// grid (30, 8), block (64, 4) — each thread gathers 4 vertices
__global__ __launch_bounds__(256) void k_skel_part(
    const int* __restrict__ joint_idx, const int* __restrict__ add_idx,
    const float* __restrict__ out)
{
    int j = blockIdx.x, ch = blockIdx.y;
    const int* row = (j < 23) ? (joint_idx + j * 128) : (add_idx + (j - 23) * 128);

    __shared__ int vs[16];
    int tid = threadIdx.y * 64 + threadIdx.x;
    if (tid < 16) vs[tid] = row[ch * 16 + tid];
    __syncthreads();

    int b = threadIdx.x, q = threadIdx.y;
    float mn0 = 3.4e38f, mn1 = 3.4e38f, mn2 = 3.4e38f;
    float mx0 = -3.4e38f, mx1 = -3.4e38f, mx2 = -3.4e38f;
    #pragma unroll
    for (int i = 0; i < 4; i++) {
        int v = vs[q * 4 + i];
        const float* p = out + ((size_t)b * 40000 + v) * 3;
        float x = p[0], y = p[1], z = p[2];
        mn0 = fminf(mn0, x); mx0 = fmaxf(mx0, x);
        mn1 = fminf(mn1, y); mx1 = fmaxf(mx1, y);
        mn2 = fminf(mn2, z); mx2 = fmaxf(mx2, z);
    }
    __shared__ float red[4][64][6];
    red[q][b][0] = mn0; red[q][b][1] = mn1; red[q][b][2] = mn2;
    red[q][b][3] = mx0; red[q][b][4] = mx1; red[q][b][5] = mx2;
    __syncthreads();
    if (q == 0) {
        #pragma unroll
        for (int c = 1; c < 4; c++) {
            mn0 = fminf(mn0, red[c][b][0]); mn1 = fminf(mn1, red[c][b][1]); mn2 = fminf(mn2, red[c][b][2]);
            mx0 = fmaxf(mx0, red[c][b][3]); mx1 = fmaxf(mx1, red[c][b][4]); mx2 = fmaxf(mx2, red[c][b][5]);
        }
        float* dst = g_spart + ((size_t)(j * 8 + ch) * 64 + b) * 6;
        dst[0] = mn0; dst[1] = mn1; dst[2] = mn2;
        dst[3] = mx0; dst[4] = mx1; dst[5] = mx2;
    }
}

// ---------------- Kernel C2: combine skeleton partials ----------------
__global__ void k_skel_comb(float* __restrict__ out)
{
    int j = blockIdx.x, b = threadIdx.x;
    int orow = (j < 23) ? (1 + j) : (24 + (j - 23));
    float mn0 = 3.4e38f, mn1 = 3.4e38f, mn2 = 3.4e38f;
    float mx0 = -3.4e38f, mx1 = -3.4e38f, mx2 = -3.4e38f;
    #pragma unroll
    for (int ch = 0; ch < 8; ch++) {
        const float* s = g_spart + ((size_t)(j * 8 + ch) * 64 + b) * 6;
        mn0 = fminf(mn0, s[0]); mn1 = fminf(mn1, s[1]); mn2 = fminf(mn2, s[2]);
        mx0 = fmaxf(mx0, s[3]); mx1 = fmaxf(mx1, s[4]); mx2 = fmaxf(mx2, s[5]);
    }
    float* s = out + SKEL_OFF + ((size_t)b * 31 + orow) * 3;
    s[0] = 0.5f * (mn0 + mx0);
    s[1] = 0.5f * (mn1 + mx1);
    s[2] = 0.5f * (mn2 + mx2);
    if (j == 0) {
        float* z0 = out + SKEL_OFF + (size_t)b * 31 * 3;
        z0[0] = 0.f; z0[1] = 0.f; z0[2] = 0.f;
    }
}

// ---------------- launch ----------------
extern "C" void kernel_launch(void* const* d_in, const int* in_sizes, int n_in,
                              void* d_out, int out_size)
{
    const float* beta      = (const float*)d_in[0];
    const float* pose      = (const float*)d_in[1];
    const float* trans     = (const float*)d_in[2];
    const float* sd        = (const float*)d_in[3];
    const float* vt        = (const float*)d_in[4];
    const float* wts       = (const float*)d_in[5];
    const int*   joint_idx = (const int*)d_in[8];
    const int*   add_idx   = (const int*)d_in[9];
    float* out = (float*)d_out;

    cudaFuncSetAttribute(k_joint_gather, cudaFuncAttributeMaxDynamicSharedMemorySize, 64000);
    cudaFuncSetAttribute(k_main,         cudaFuncAttributeMaxDynamicSharedMemorySize, SM_TOT * 4);

    k_joint_gather<<<dim3(23, 4), dim3(32, 8), 64000>>>(beta, sd, vt, joint_idx);
    k_chain<<<64, 32>>>(pose);
    k_main<<<dim3(1250, 2), dim3(32, 8), SM_TOT * 4>>>(beta, trans, sd, vt, wts, out);
    k_skel_part<<<dim3(30, 8), dim3(64, 4)>>>(joint_idx, add_idx, out);
    k_skel_comb<<<30, 64>>>(out);
}

// round 9
// speedup vs baseline: 1.0662x; 1.0417x over previous
#include <cuda_runtime.h>
#include <math.h>
#include <stdint.h>

#define B_   64
#define NV   40000
#define P_   100
#define NJ   24
#define SKEL_OFF 7680000   // 64*40000*3

// ---------------- scratch (device globals; no allocation allowed) ----------------
__device__ float g_G1[B_ * NJ * 12];
__device__ float g_part[23 * 4 * B_ * 6];
__device__ float g_spart[30 * 8 * B_ * 6];
__device__ int   g_cnt[30];   // zero-initialized; returns to 0 after each replay

// ---------------- cp.async helpers ----------------
__device__ __forceinline__ void cp16(uint32_t dst, const void* src) {
    asm volatile("cp.async.cg.shared.global [%0], [%1], 16;" :: "r"(dst), "l"(src));
}
__device__ __forceinline__ void cp_commit() {
    asm volatile("cp.async.commit_group;");
}
template <int N>
__device__ __forceinline__ void cp_wait() {
    asm volatile("cp.async.wait_group %0;" :: "n"(N));
}

// ---------------- Kernel A1: gathered v_posed + per-chunk min/max ----------------
// grid (23, 4), block (32, 8)
__global__ __launch_bounds__(256) void k_joint_gather(
    const float* __restrict__ beta, const float* __restrict__ sd,
    const float* __restrict__ vt, const int* __restrict__ joint_idx)
{
    extern __shared__ float sm[];
    float* beta_s = sm;          // [64][100]
    float* sd_cs  = sm + 6400;   // [100][96]
    __shared__ int idxs[32];

    int j = blockIdx.x, ch = blockIdx.y;
    int tid = threadIdx.y * 32 + threadIdx.x;

    if (tid < 32) idxs[tid] = joint_idx[j * 128 + ch * 32 + tid];
    for (int i = tid; i < 6400; i += 256) beta_s[i] = beta[i];
    __syncthreads();

    for (int i = tid; i < 3200; i += 256) {
        int p = i >> 5, s = i & 31;
        size_t base = (size_t)p * 120000 + 3 * idxs[s];
        sd_cs[p * 96 + s * 3 + 0] = sd[base + 0];
        sd_cs[p * 96 + s * 3 + 1] = sd[base + 1];
        sd_cs[p * 96 + s * 3 + 2] = sd[base + 2];
    }
    __syncthreads();

    int lane = threadIdx.x, y = threadIdx.y;
    float acc[24];
    #pragma unroll
    for (int t = 0; t < 24; t++) acc[t] = 0.f;

    for (int p = 0; p < 100; p++) {
        float s0 = sd_cs[p * 96 + lane * 3 + 0];
        float s1 = sd_cs[p * 96 + lane * 3 + 1];
        float s2 = sd_cs[p * 96 + lane * 3 + 2];
        #pragma unroll
        for (int bb = 0; bb < 8; bb++) {
            float bp = beta_s[(y * 8 + bb) * 100 + p];
            acc[bb * 3 + 0] = fmaf(bp, s0, acc[bb * 3 + 0]);
            acc[bb * 3 + 1] = fmaf(bp, s1, acc[bb * 3 + 1]);
            acc[bb * 3 + 2] = fmaf(bp, s2, acc[bb * 3 + 2]);
        }
    }
    int myidx = idxs[lane];
    float v0 = vt[3 * myidx + 0], v1 = vt[3 * myidx + 1], v2 = vt[3 * myidx + 2];
    #pragma unroll
    for (int bb = 0; bb < 8; bb++) {
        acc[bb * 3 + 0] += v0; acc[bb * 3 + 1] += v1; acc[bb * 3 + 2] += v2;
    }
    float mx[24];
    #pragma unroll
    for (int t = 0; t < 24; t++) mx[t] = acc[t];

    for (int off = 16; off; off >>= 1) {
        #pragma unroll
        for (int t = 0; t < 24; t++) {
            float om = __shfl_xor_sync(0xffffffffu, acc[t], off);
            float ox = __shfl_xor_sync(0xffffffffu, mx[t],  off);
            acc[t] = fminf(acc[t], om);
            mx[t]  = fmaxf(mx[t],  ox);
        }
    }
    if (lane < 8) {
        int b = y * 8 + lane;
        float* dst = g_part + ((size_t)(j * 4 + ch) * 64 + b) * 6;
        dst[0] = acc[lane * 3 + 0]; dst[1] = acc[lane * 3 + 1]; dst[2] = acc[lane * 3 + 2];
        dst[3] = mx[lane * 3 + 0];  dst[4] = mx[lane * 3 + 1];  dst[5] = mx[lane * 3 + 2];
    }
}

// ---------------- Kernel A2: chunk-reduce + Rodrigues + kinematic chain -> G1 ----
__global__ void k_chain(const float* __restrict__ pose)
{
    int b = blockIdx.x, t = threadIdx.x;
    __shared__ float R[24][9], Jl[24][3], Gr[24][9], Gt[24][3];

    if (t < 24) {
        if (t == 0) {
            Jl[0][0] = 0.f; Jl[0][1] = 0.f; Jl[0][2] = 0.f;
        } else {
            int j = t - 1;
            float mn0 = 3.4e38f, mn1 = 3.4e38f, mn2 = 3.4e38f;
            float mx0 = -3.4e38f, mx1 = -3.4e38f, mx2 = -3.4e38f;
            #pragma unroll
            for (int ch = 0; ch < 4; ch++) {
                const float* s = g_part + ((size_t)(j * 4 + ch) * 64 + b) * 6;
                mn0 = fminf(mn0, s[0]); mn1 = fminf(mn1, s[1]); mn2 = fminf(mn2, s[2]);
                mx0 = fmaxf(mx0, s[3]); mx1 = fmaxf(mx1, s[4]); mx2 = fmaxf(mx2, s[5]);
            }
            Jl[t][0] = 0.5f * (mn0 + mx0);
            Jl[t][1] = 0.5f * (mn1 + mx1);
            Jl[t][2] = 0.5f * (mn2 + mx2);
        }

        float rx = pose[b * 72 + t * 3 + 0];
        float ry = pose[b * 72 + t * 3 + 1];
        float rz = pose[b * 72 + t * 3 + 2];
        float th = sqrtf(rx * rx + ry * ry + rz * rz);
        th = fmaxf(th, 1e-6f);
        float s, c;
        sincosf(th, &s, &c);
        float inv = 1.0f / th;
        float x = rx * inv, y = ry * inv, z = rz * inv;
        float omc = 1.0f - c;
        R[t][0] = c + omc * x * x;     R[t][1] = omc * x * y - s * z; R[t][2] = omc * x * z + s * y;
        R[t][3] = omc * x * y + s * z; R[t][4] = c + omc * y * y;     R[t][5] = omc * y * z - s * x;
        R[t][6] = omc * x * z - s * y; R[t][7] = omc * y * z + s * x; R[t][8] = c + omc * z * z;
    }
    __syncthreads();

    if (t == 0) {
        for (int q = 0; q < 9; q++) Gr[0][q] = R[0][q];
        Gt[0][0] = Jl[0][0]; Gt[0][1] = Jl[0][1]; Gt[0][2] = Jl[0][2];
        for (int i = 1; i < 24; i++) {
            int p = (i - 1) >> 1;
            for (int r = 0; r < 3; r++)
                for (int cc = 0; cc < 3; cc++)
                    Gr[i][r * 3 + cc] = Gr[p][r * 3 + 0] * R[i][0 + cc]
                                      + Gr[p][r * 3 + 1] * R[i][3 + cc]
                                      + Gr[p][r * 3 + 2] * R[i][6 + cc];
            float dx = Jl[i][0] - Jl[p][0];
            float dy = Jl[i][1] - Jl[p][1];
            float dz = Jl[i][2] - Jl[p][2];
            for (int r = 0; r < 3; r++)
                Gt[i][r] = Gr[p][r * 3 + 0] * dx + Gr[p][r * 3 + 1] * dy
                         + Gr[p][r * 3 + 2] * dz + Gt[p][r];
        }
    }
    __syncthreads();

    if (t < 24) {
        float* d = g_G1 + ((size_t)b * 24 + t) * 12;
        for (int r = 0; r < 3; r++) {
            float tc = Gr[t][r * 3 + 0] * Jl[t][0] + Gr[t][r * 3 + 1] * Jl[t][1]
                     + Gr[t][r * 3 + 2] * Jl[t][2];
            d[r * 4 + 0] = Gr[t][r * 3 + 0];
            d[r * 4 + 1] = Gr[t][r * 3 + 1];
            d[r * 4 + 2] = Gr[t][r * 3 + 2];
            d[r * 4 + 3] = Gt[t][r] - tc;
        }
    }
}

// ---------------- Kernel B: fused shape blend + skinning (R5 version) -----------
// grid (1250, 2), block (32, 8) = 256 threads, 4 vertices/thread
#define PC 25
#define SM_G1    0
#define SM_W     (24 * 32 * 12)                  // 9216
#define SM_BETA  (SM_W + 24 * 32)                // 9984
#define SM_SD    ((SM_BETA + 100 * 33 + 3) & ~3) // 13288 (16B aligned)
#define SM_TOT   (SM_SD + 2 * PC * 96)           // 18088 floats = 72352 B

__global__ __launch_bounds__(256, 3) void k_main(
    const float* __restrict__ beta, const float* __restrict__ trans,
    const float* __restrict__ sd, const float* __restrict__ vt,
    const float* __restrict__ wts, float* __restrict__ out)
{
    extern __shared__ float sm[];
    float* g1_s   = sm + SM_G1;
    float* w_s    = sm + SM_W;
    float* beta_s = sm + SM_BETA;

    int tid = threadIdx.y * 32 + threadIdx.x;
    int n0 = blockIdx.x * 32;
    int b0 = blockIdx.y * 32;

    uint32_t sd_sm_u32 = (uint32_t)__cvta_generic_to_shared(sm + SM_SD);
    const float* sd_blk = sd + 3 * n0;

    // prefetch sd chunk 0 into buffer 0
    {
        const float* base = sd_blk;
        for (int i = tid; i < 600; i += 256) {
            int p = i / 24, q = i - p * 24;
            cp16(sd_sm_u32 + (uint32_t)i * 16, base + (size_t)p * 120000 + q * 4);
        }
        cp_commit();
    }

    // one-time stages: G1 + weights + full beta transpose
    for (int i = tid; i < 2304; i += 256) {
        int bb = i / 72, r = i - bb * 72;
        int k = r / 3, j4 = r - k * 3;
        ((float4*)g1_s)[(k * 32 + bb) * 3 + j4] =
            *(const float4*)(g_G1 + (size_t)(b0 + bb) * 288 + r * 4);
    }
    for (int i = tid; i < 768; i += 256) {
        int k = i >> 5, vl = i & 31;
        w_s[k * 32 + vl] = wts[(size_t)(n0 + vl) * 24 + k];
    }
    for (int i = tid; i < 3200; i += 256) {
        int p = i >> 5, bb = i & 31;
        beta_s[p * 33 + bb] = beta[(b0 + bb) * 100 + p];
    }

    int b = threadIdx.x, vl0 = threadIdx.y * 4;

    float acc[12];
    {
        const float4* v4 = (const float4*)(vt + (size_t)(n0 + vl0) * 3);
        float4 a = v4[0], b4 = v4[1], c4 = v4[2];
        acc[0] = a.x; acc[1] = a.y; acc[2] = a.z; acc[3] = a.w;
        acc[4] = b4.x; acc[5] = b4.y; acc[6] = b4.z; acc[7] = b4.w;
        acc[8] = c4.x; acc[9] = c4.y; acc[10] = c4.z; acc[11] = c4.w;
    }

    // pipelined shape blend over 4 chunks of PC=25
    #pragma unroll
    for (int c = 0; c < 4; c++) {
        if (c < 3) {
            const float* base = sd_blk + (size_t)((c + 1) * PC) * 120000;
            uint32_t dstb = sd_sm_u32 + (uint32_t)(((c + 1) & 1) * 600) * 16;
            for (int i = tid; i < 600; i += 256) {
                int p = i / 24, q = i - p * 24;
                cp16(dstb + (uint32_t)i * 16, base + (size_t)p * 120000 + q * 4);
            }
            cp_commit();
            cp_wait<1>();
        } else {
            cp_wait<0>();
        }
        __syncthreads();

        const float4* sdp = ((const float4*)(sm + SM_SD)) + (c & 1) * 600 + threadIdx.y * 3;
        const float* bcol = beta_s + c * PC * 33 + b;
        #pragma unroll 5
        for (int p = 0; p < PC; p++) {
            float bp = bcol[p * 33];
            float4 s0 = sdp[p * 24 + 0];
            float4 s1 = sdp[p * 24 + 1];
            float4 s2 = sdp[p * 24 + 2];
            acc[0]  = fmaf(bp, s0.x, acc[0]);
            acc[1]  = fmaf(bp, s0.y, acc[1]);
            acc[2]  = fmaf(bp, s0.z, acc[2]);
            acc[3]  = fmaf(bp, s0.w, acc[3]);
            acc[4]  = fmaf(bp, s1.x, acc[4]);
            acc[5]  = fmaf(bp, s1.y, acc[5]);
            acc[6]  = fmaf(bp, s1.z, acc[6]);
            acc[7]  = fmaf(bp, s1.w, acc[7]);
            acc[8]  = fmaf(bp, s2.x, acc[8]);
            acc[9]  = fmaf(bp, s2.y, acc[9]);
            acc[10] = fmaf(bp, s2.z, acc[10]);
            acc[11] = fmaf(bp, s2.w, acc[11]);
        }
        __syncthreads();
    }

    float tr0 = trans[(b0 + b) * 3 + 0];
    float tr1 = trans[(b0 + b) * 3 + 1];
    float tr2 = trans[(b0 + b) * 3 + 2];
    float o[12] = {tr0, tr1, tr2, tr0, tr1, tr2, tr0, tr1, tr2, tr0, tr1, tr2};

    #pragma unroll 4
    for (int k = 0; k < 24; k++) {
        const float4* g = (const float4*)(g1_s + (k * 32 + b) * 12);
        float4 g0 = g[0], g1v = g[1], g2 = g[2];
        float4 w4 = *(const float4*)(w_s + k * 32 + vl0);
        float wv[4] = {w4.x, w4.y, w4.z, w4.w};
        #pragma unroll
        for (int vi = 0; vi < 4; vi++) {
            float vx = acc[vi * 3 + 0], vy = acc[vi * 3 + 1], vz = acc[vi * 3 + 2];
            float t0 = fmaf(g0.x,  vx, fmaf(g0.y,  vy, fmaf(g0.z,  vz, g0.w)));
            float t1 = fmaf(g1v.x, vx, fmaf(g1v.y, vy, fmaf(g1v.z, vz, g1v.w)));
            float t2 = fmaf(g2.x,  vx, fmaf(g2.y,  vy, fmaf(g2.z,  vz, g2.w)));
            o[vi * 3 + 0] = fmaf(wv[vi], t0, o[vi * 3 + 0]);
            o[vi * 3 + 1] = fmaf(wv[vi], t1, o[vi * 3 + 1]);
            o[vi * 3 + 2] = fmaf(wv[vi], t2, o[vi * 3 + 2]);
        }
    }

    float4* dst = (float4*)(out + ((size_t)(b0 + b) * 40000 + n0 + vl0) * 3);
    dst[0] = make_float4(o[0], o[1], o[2],  o[3]);
    dst[1] = make_float4(o[4], o[5], o[6],  o[7]);
    dst[2] = make_float4(o[8], o[9], o[10], o[11]);
}

// ---------------- Kernel C: skeleton partials + fused final reduction -----------
// grid (30, 8), block (64, 4); last-arriving block per row finalizes.
__global__ __launch_bounds__(256) void k_skel_part(
    const int* __restrict__ joint_idx, const int* __restrict__ add_idx,
    float* __restrict__ out)
{
    int j = blockIdx.x, ch = blockIdx.y;
    const int* row = (j < 23) ? (joint_idx + j * 128) : (add_idx + (j - 23) * 128);

    __shared__ int vs[16];
    __shared__ int ticket;
    int tid = threadIdx.y * 64 + threadIdx.x;
    if (tid < 16) vs[tid] = row[ch * 16 + tid];
    __syncthreads();

    int b = threadIdx.x, q = threadIdx.y;
    float mn0 = 3.4e38f, mn1 = 3.4e38f, mn2 = 3.4e38f;
    float mx0 = -3.4e38f, mx1 = -3.4e38f, mx2 = -3.4e38f;
    #pragma unroll
    for (int i = 0; i < 4; i++) {
        int v = vs[q * 4 + i];
        const float* p = out + ((size_t)b * 40000 + v) * 3;
        float x = p[0], y = p[1], z = p[2];
        mn0 = fminf(mn0, x); mx0 = fmaxf(mx0, x);
        mn1 = fminf(mn1, y); mx1 = fmaxf(mx1, y);
        mn2 = fminf(mn2, z); mx2 = fmaxf(mx2, z);
    }
    __shared__ float red[4][64][6];
    red[q][b][0] = mn0; red[q][b][1] = mn1; red[q][b][2] = mn2;
    red[q][b][3] = mx0; red[q][b][4] = mx1; red[q][b][5] = mx2;
    __syncthreads();
    if (q == 0) {
        #pragma unroll
        for (int c = 1; c < 4; c++) {
            mn0 = fminf(mn0, red[c][b][0]); mn1 = fminf(mn1, red[c][b][1]); mn2 = fminf(mn2, red[c][b][2]);
            mx0 = fmaxf(mx0, red[c][b][3]); mx1 = fmaxf(mx1, red[c][b][4]); mx2 = fmaxf(mx2, red[c][b][5]);
        }
        float* dst = g_spart + ((size_t)(j * 8 + ch) * 64 + b) * 6;
        dst[0] = mn0; dst[1] = mn1; dst[2] = mn2;
        dst[3] = mx0; dst[4] = mx1; dst[5] = mx2;
    }

    // threadfence-reduction handoff: last block of the 8 chunks finalizes row j
    __threadfence();
    __syncthreads();
    if (tid == 0) ticket = atomicAdd(&g_cnt[j], 1);
    __syncthreads();
    if (ticket == 7) {
        __threadfence();
        if (q == 0) {
            int orow = (j < 23) ? (1 + j) : (24 + (j - 23));
            float fn0 = 3.4e38f, fn1 = 3.4e38f, fn2 = 3.4e38f;
            float fx0 = -3.4e38f, fx1 = -3.4e38f, fx2 = -3.4e38f;
            #pragma unroll
            for (int c = 0; c < 8; c++) {
                const float* s = g_spart + ((size_t)(j * 8 + c) * 64 + b) * 6;
                fn0 = fminf(fn0, s[0]); fn1 = fminf(fn1, s[1]); fn2 = fminf(fn2, s[2]);
                fx0 = fmaxf(fx0, s[3]); fx1 = fmaxf(fx1, s[4]); fx2 = fmaxf(fx2, s[5]);
            }
            float* s = out + SKEL_OFF + ((size_t)b * 31 + orow) * 3;
            s[0] = 0.5f * (fn0 + fx0);
            s[1] = 0.5f * (fn1 + fx1);
            s[2] = 0.5f * (fn2 + fx2);
            if (j == 0) {
                float* z0 = out + SKEL_OFF + (size_t)b * 31 * 3;
                z0[0] = 0.f; z0[1] = 0.f; z0[2] = 0.f;
            }
        }
        if (tid == 0) atomicExch(&g_cnt[j], 0);   // reset for next graph replay
    }
}

// ---------------- launch ----------------
extern "C" void kernel_launch(void* const* d_in, const int* in_sizes, int n_in,
                              void* d_out, int out_size)
{
    const float* beta      = (const float*)d_in[0];
    const float* pose      = (const float*)d_in[1];
    const float* trans     = (const float*)d_in[2];
    const float* sd        = (const float*)d_in[3];
    const float* vt        = (const float*)d_in[4];
    const float* wts       = (const float*)d_in[5];
    const int*   joint_idx = (const int*)d_in[8];
    const int*   add_idx   = (const int*)d_in[9];
    float* out = (float*)d_out;

    cudaFuncSetAttribute(k_joint_gather, cudaFuncAttributeMaxDynamicSharedMemorySize, 64000);
    cudaFuncSetAttribute(k_main,         cudaFuncAttributeMaxDynamicSharedMemorySize, SM_TOT * 4);

    k_joint_gather<<<dim3(23, 4), dim3(32, 8), 64000>>>(beta, sd, vt, joint_idx);
    k_chain<<<64, 32>>>(pose);
    k_main<<<dim3(1250, 2), dim3(32, 8), SM_TOT * 4>>>(beta, trans, sd, vt, wts, out);
    k_skel_part<<<dim3(30, 8), dim3(64, 4)>>>(joint_idx, add_idx, out);
}

// round 10
// speedup vs baseline: 1.1788x; 1.1056x over previous
#include <cuda_runtime.h>
#include <math.h>
#include <stdint.h>

#define B_   64
#define NV   40000
#define P_   100
#define NJ   24
#define SKEL_OFF 7680000   // 64*40000*3

// ---------------- scratch (device globals; no allocation allowed) ----------------
__device__ float g_G1[B_ * NJ * 12];
__device__ float g_part[23 * 4 * B_ * 6];
__device__ float g_spart[30 * 8 * B_ * 6];
__device__ int   g_cnt[30];   // zero-initialized; returns to 0 after each replay

// ---------------- cp.async helpers ----------------
__device__ __forceinline__ void cp16(uint32_t dst, const void* src) {
    asm volatile("cp.async.cg.shared.global [%0], [%1], 16;" :: "r"(dst), "l"(src));
}
__device__ __forceinline__ void cp_commit() {
    asm volatile("cp.async.commit_group;");
}
template <int N>
__device__ __forceinline__ void cp_wait() {
    asm volatile("cp.async.wait_group %0;" :: "n"(N));
}

// ---------------- tf32 mma helpers ----------------
__device__ __forceinline__ uint32_t f2tf32(float f) {
    uint32_t u; asm("cvt.rna.tf32.f32 %0, %1;" : "=r"(u) : "f"(f)); return u;
}
__device__ __forceinline__ void mma_tf32(float c[4],
    uint32_t a0, uint32_t a1, uint32_t a2, uint32_t a3,
    uint32_t b0, uint32_t b1)
{
    asm volatile(
        "mma.sync.aligned.m16n8k8.row.col.f32.tf32.tf32.f32 "
        "{%0,%1,%2,%3},{%4,%5,%6,%7},{%8,%9},{%0,%1,%2,%3};"
        : "+f"(c[0]), "+f"(c[1]), "+f"(c[2]), "+f"(c[3])
        : "r"(a0), "r"(a1), "r"(a2), "r"(a3), "r"(b0), "r"(b1));
}

// ---------------- Kernel A1: gathered v_posed + per-chunk min/max ----------------
// grid (23, 4), block (32, 8)
__global__ __launch_bounds__(256) void k_joint_gather(
    const float* __restrict__ beta, const float* __restrict__ sd,
    const float* __restrict__ vt, const int* __restrict__ joint_idx)
{
    extern __shared__ float sm[];
    float* beta_s = sm;          // [64][100]
    float* sd_cs  = sm + 6400;   // [100][96]
    __shared__ int idxs[32];

    int j = blockIdx.x, ch = blockIdx.y;
    int tid = threadIdx.y * 32 + threadIdx.x;

    if (tid < 32) idxs[tid] = joint_idx[j * 128 + ch * 32 + tid];
    for (int i = tid; i < 6400; i += 256) beta_s[i] = beta[i];
    __syncthreads();

    for (int i = tid; i < 3200; i += 256) {
        int p = i >> 5, s = i & 31;
        size_t base = (size_t)p * 120000 + 3 * idxs[s];
        sd_cs[p * 96 + s * 3 + 0] = sd[base + 0];
        sd_cs[p * 96 + s * 3 + 1] = sd[base + 1];
        sd_cs[p * 96 + s * 3 + 2] = sd[base + 2];
    }
    __syncthreads();

    int lane = threadIdx.x, y = threadIdx.y;
    float acc[24];
    #pragma unroll
    for (int t = 0; t < 24; t++) acc[t] = 0.f;

    for (int p = 0; p < 100; p++) {
        float s0 = sd_cs[p * 96 + lane * 3 + 0];
        float s1 = sd_cs[p * 96 + lane * 3 + 1];
        float s2 = sd_cs[p * 96 + lane * 3 + 2];
        #pragma unroll
        for (int bb = 0; bb < 8; bb++) {
            float bp = beta_s[(y * 8 + bb) * 100 + p];
            acc[bb * 3 + 0] = fmaf(bp, s0, acc[bb * 3 + 0]);
            acc[bb * 3 + 1] = fmaf(bp, s1, acc[bb * 3 + 1]);
            acc[bb * 3 + 2] = fmaf(bp, s2, acc[bb * 3 + 2]);
        }
    }
    int myidx = idxs[lane];
    float v0 = vt[3 * myidx + 0], v1 = vt[3 * myidx + 1], v2 = vt[3 * myidx + 2];
    #pragma unroll
    for (int bb = 0; bb < 8; bb++) {
        acc[bb * 3 + 0] += v0; acc[bb * 3 + 1] += v1; acc[bb * 3 + 2] += v2;
    }
    float mx[24];
    #pragma unroll
    for (int t = 0; t < 24; t++) mx[t] = acc[t];

    for (int off = 16; off; off >>= 1) {
        #pragma unroll
        for (int t = 0; t < 24; t++) {
            float om = __shfl_xor_sync(0xffffffffu, acc[t], off);
            float ox = __shfl_xor_sync(0xffffffffu, mx[t],  off);
            acc[t] = fminf(acc[t], om);
            mx[t]  = fmaxf(mx[t],  ox);
        }
    }
    if (lane < 8) {
        int b = y * 8 + lane;
        float* dst = g_part + ((size_t)(j * 4 + ch) * 64 + b) * 6;
        dst[0] = acc[lane * 3 + 0]; dst[1] = acc[lane * 3 + 1]; dst[2] = acc[lane * 3 + 2];
        dst[3] = mx[lane * 3 + 0];  dst[4] = mx[lane * 3 + 1];  dst[5] = mx[lane * 3 + 2];
    }
}

// ---------------- Kernel A2: chunk-reduce + Rodrigues + kinematic chain -> G1 ----
__global__ void k_chain(const float* __restrict__ pose)
{
    int b = blockIdx.x, t = threadIdx.x;
    __shared__ float R[24][9], Jl[24][3], Gr[24][9], Gt[24][3];

    if (t < 24) {
        if (t == 0) {
            Jl[0][0] = 0.f; Jl[0][1] = 0.f; Jl[0][2] = 0.f;
        } else {
            int j = t - 1;
            float mn0 = 3.4e38f, mn1 = 3.4e38f, mn2 = 3.4e38f;
            float mx0 = -3.4e38f, mx1 = -3.4e38f, mx2 = -3.4e38f;
            #pragma unroll
            for (int ch = 0; ch < 4; ch++) {
                const float* s = g_part + ((size_t)(j * 4 + ch) * 64 + b) * 6;
                mn0 = fminf(mn0, s[0]); mn1 = fminf(mn1, s[1]); mn2 = fminf(mn2, s[2]);
                mx0 = fmaxf(mx0, s[3]); mx1 = fmaxf(mx1, s[4]); mx2 = fmaxf(mx2, s[5]);
            }
            Jl[t][0] = 0.5f * (mn0 + mx0);
            Jl[t][1] = 0.5f * (mn1 + mx1);
            Jl[t][2] = 0.5f * (mn2 + mx2);
        }

        float rx = pose[b * 72 + t * 3 + 0];
        float ry = pose[b * 72 + t * 3 + 1];
        float rz = pose[b * 72 + t * 3 + 2];
        float th = sqrtf(rx * rx + ry * ry + rz * rz);
        th = fmaxf(th, 1e-6f);
        float s, c;
        sincosf(th, &s, &c);
        float inv = 1.0f / th;
        float x = rx * inv, y = ry * inv, z = rz * inv;
        float omc = 1.0f - c;
        R[t][0] = c + omc * x * x;     R[t][1] = omc * x * y - s * z; R[t][2] = omc * x * z + s * y;
        R[t][3] = omc * x * y + s * z; R[t][4] = c + omc * y * y;     R[t][5] = omc * y * z - s * x;
        R[t][6] = omc * x * z - s * y; R[t][7] = omc * y * z + s * x; R[t][8] = c + omc * z * z;
    }
    __syncthreads();

    if (t == 0) {
        for (int q = 0; q < 9; q++) Gr[0][q] = R[0][q];
        Gt[0][0] = Jl[0][0]; Gt[0][1] = Jl[0][1]; Gt[0][2] = Jl[0][2];
        for (int i = 1; i < 24; i++) {
            int p = (i - 1) >> 1;
            for (int r = 0; r < 3; r++)
                for (int cc = 0; cc < 3; cc++)
                    Gr[i][r * 3 + cc] = Gr[p][r * 3 + 0] * R[i][0 + cc]
                                      + Gr[p][r * 3 + 1] * R[i][3 + cc]
                                      + Gr[p][r * 3 + 2] * R[i][6 + cc];
            float dx = Jl[i][0] - Jl[p][0];
            float dy = Jl[i][1] - Jl[p][1];
            float dz = Jl[i][2] - Jl[p][2];
            for (int r = 0; r < 3; r++)
                Gt[i][r] = Gr[p][r * 3 + 0] * dx + Gr[p][r * 3 + 1] * dy
                         + Gr[p][r * 3 + 2] * dz + Gt[p][r];
        }
    }
    __syncthreads();

    if (t < 24) {
        float* d = g_G1 + ((size_t)b * 24 + t) * 12;
        for (int r = 0; r < 3; r++) {
            float tc = Gr[t][r * 3 + 0] * Jl[t][0] + Gr[t][r * 3 + 1] * Jl[t][1]
                     + Gr[t][r * 3 + 2] * Jl[t][2];
            d[r * 4 + 0] = Gr[t][r * 3 + 0];
            d[r * 4 + 1] = Gr[t][r * 3 + 1];
            d[r * 4 + 2] = Gr[t][r * 3 + 2];
            d[r * 4 + 3] = Gt[t][r] - tc;
        }
    }
}

// ---------------- Kernel B: tf32-mma shape blend + fp32 skinning ----------------
// grid (1250, 2), block (32, 8) = 256 threads (8 warps), 4 vertices/thread.
// Blend: D[32 batch x 96 cols] = beta[32x104(tf32)] @ sd[104x96], K padded w/ zeros.
// smem (floats):
//   g1  [24][32][12]            = 9216
//   w   [24][32]                = 768
//   beta A-operand [32][132]    = 4224   (pitch 132: %32==4 -> A-frag LDS conflict-free)
//   sd   B-operand [104][104]   = 10816  (pitch 104: %32==8 -> B-frag LDS conflict-free)
//   vp (aliases sd after blend) [32][100] = 3200
#define SM_G1    0
#define SM_W     9216
#define SM_BETA  (SM_W + 768)            // 9984
#define SM_SD    (SM_BETA + 32 * 132)    // 14208
#define SM_TOT   (SM_SD + 104 * 104)     // 25024 floats = 100096 B

__global__ __launch_bounds__(256, 2) void k_main(
    const float* __restrict__ beta, const float* __restrict__ trans,
    const float* __restrict__ sd, const float* __restrict__ vt,
    const float* __restrict__ wts, float* __restrict__ out)
{
    extern __shared__ float sm[];
    float* g1_s   = sm + SM_G1;
    float* w_s    = sm + SM_W;
    float* beta_s = sm + SM_BETA;
    float* sd_s   = sm + SM_SD;

    int tid = threadIdx.y * 32 + threadIdx.x;
    int n0 = blockIdx.x * 32;
    int b0 = blockIdx.y * 32;

    uint32_t sd_sm_u32 = (uint32_t)__cvta_generic_to_shared(sd_s);

    // ---- stage sd tile [100 rows][96 cols] via cp.async, pitch 104 ----
    {
        const float* base = sd + 3 * n0;
        for (int i = tid; i < 2400; i += 256) {
            int row = i / 24, q = i - row * 24;
            cp16(sd_sm_u32 + (uint32_t)(row * 416 + q * 16),
                 base + (size_t)row * 120000 + q * 4);
        }
        cp_commit();
    }
    // zero K-pad rows 100..103 (96 cols each)
    for (int i = tid; i < 96; i += 256) {
        int r = 100 + i / 24, q = i - (i / 24) * 24;
        ((float4*)sd_s)[r * 26 + q] = make_float4(0.f, 0.f, 0.f, 0.f);
    }

    // ---- stage beta A-operand, tf32-converted, [32][pitch 132], K 100->104 pad 0 ----
    for (int i = tid; i < 3328; i += 256) {
        int m = i / 104, k = i - m * 104;
        float v = (k < 100) ? beta[(size_t)(b0 + m) * 100 + k] : 0.f;
        beta_s[m * 132 + k] = __uint_as_float(f2tf32(v));
    }

    // ---- stage G1 + weights (R5 layouts, skinning unchanged) ----
    for (int i = tid; i < 2304; i += 256) {
        int bb = i / 72, r = i - bb * 72;
        int k = r / 3, j4 = r - k * 3;
        ((float4*)g1_s)[(k * 32 + bb) * 3 + j4] =
            *(const float4*)(g_G1 + (size_t)(b0 + bb) * 288 + r * 4);
    }
    for (int i = tid; i < 768; i += 256) {
        int k = i >> 5, vl = i & 31;
        w_s[k * 32 + vl] = wts[(size_t)(n0 + vl) * 24 + k];
    }

    cp_wait<0>();
    __syncthreads();

    // ---- tf32 mma blend: warp w -> mtile = w>>2, ntiles {3*(w&3) .. +2} ----
    int wid  = threadIdx.y;
    int lane = threadIdx.x;
    int gid  = lane >> 2, tig = lane & 3;
    int mtile = wid >> 2;
    int ntile0 = (wid & 3) * 3;

    float c[3][4];
    #pragma unroll
    for (int t = 0; t < 3; t++)
        #pragma unroll
        for (int q = 0; q < 4; q++) c[t][q] = 0.f;

    const float* ap = beta_s + (mtile * 16 + gid) * 132 + tig;
    const float* bp = sd_s + tig * 104 + ntile0 * 8 + gid;

    #pragma unroll
    for (int ks = 0; ks < 13; ks++) {
        int ko = ks * 8;
        uint32_t a0 = __float_as_uint(ap[ko]);
        uint32_t a1 = __float_as_uint(ap[ko + 8 * 132]);
        uint32_t a2 = __float_as_uint(ap[ko + 4]);
        uint32_t a3 = __float_as_uint(ap[ko + 4 + 8 * 132]);
        const float* bk = bp + ko * 104;
        uint32_t b00 = __float_as_uint(bk[0]);
        uint32_t b01 = __float_as_uint(bk[4 * 104]);
        uint32_t b10 = __float_as_uint(bk[8]);
        uint32_t b11 = __float_as_uint(bk[8 + 4 * 104]);
        uint32_t b20 = __float_as_uint(bk[16]);
        uint32_t b21 = __float_as_uint(bk[16 + 4 * 104]);
        mma_tf32(c[0], a0, a1, a2, a3, b00, b01);
        mma_tf32(c[1], a0, a1, a2, a3, b10, b11);
        mma_tf32(c[2], a0, a1, a2, a3, b20, b21);
    }

    __syncthreads();   // all sd reads done; safe to overwrite with vp

    // ---- redistribute D -> vp[m=batch][pitch 100] ----
    {
        float* vp = sd_s;
        int mrow = mtile * 16 + gid;
        #pragma unroll
        for (int t = 0; t < 3; t++) {
            int ncol = (ntile0 + t) * 8 + 2 * tig;
            *(float2*)(vp + mrow * 100 + ncol)       = make_float2(c[t][0], c[t][1]);
            *(float2*)(vp + (mrow + 8) * 100 + ncol) = make_float2(c[t][2], c[t][3]);
        }
    }
    __syncthreads();

    // ---- epilogue: acc = vp + vt, then fp32 skinning (identical to R9) ----
    int b = threadIdx.x, vl0 = threadIdx.y * 4;

    float acc[12];
    {
        const float4* vprow = (const float4*)(sd_s + b * 100 + vl0 * 3);
        const float4* v4 = (const float4*)(vt + (size_t)(n0 + vl0) * 3);
        float4 p0 = vprow[0], p1 = vprow[1], p2 = vprow[2];
        float4 a = v4[0], b4 = v4[1], c4 = v4[2];
        acc[0] = p0.x + a.x;  acc[1] = p0.y + a.y;  acc[2]  = p0.z + a.z;  acc[3]  = p0.w + a.w;
        acc[4] = p1.x + b4.x; acc[5] = p1.y + b4.y; acc[6]  = p1.z + b4.z; acc[7]  = p1.w + b4.w;
        acc[8] = p2.x + c4.x; acc[9] = p2.y + c4.y; acc[10] = p2.z + c4.z; acc[11] = p2.w + c4.w;
    }

    float tr0 = trans[(b0 + b) * 3 + 0];
    float tr1 = trans[(b0 + b) * 3 + 1];
    float tr2 = trans[(b0 + b) * 3 + 2];
    float o[12] = {tr0, tr1, tr2, tr0, tr1, tr2, tr0, tr1, tr2, tr0, tr1, tr2};

    #pragma unroll 4
    for (int k = 0; k < 24; k++) {
        const float4* g = (const float4*)(g1_s + (k * 32 + b) * 12);
        float4 g0 = g[0], g1v = g[1], g2 = g[2];
        float4 w4 = *(const float4*)(w_s + k * 32 + vl0);
        float wv[4] = {w4.x, w4.y, w4.z, w4.w};
        #pragma unroll
        for (int vi = 0; vi < 4; vi++) {
            float vx = acc[vi * 3 + 0], vy = acc[vi * 3 + 1], vz = acc[vi * 3 + 2];
            float t0 = fmaf(g0.x,  vx, fmaf(g0.y,  vy, fmaf(g0.z,  vz, g0.w)));
            float t1 = fmaf(g1v.x, vx, fmaf(g1v.y, vy, fmaf(g1v.z, vz, g1v.w)));
            float t2 = fmaf(g2.x,  vx, fmaf(g2.y,  vy, fmaf(g2.z,  vz, g2.w)));
            o[vi * 3 + 0] = fmaf(wv[vi], t0, o[vi * 3 + 0]);
            o[vi * 3 + 1] = fmaf(wv[vi], t1, o[vi * 3 + 1]);
            o[vi * 3 + 2] = fmaf(wv[vi], t2, o[vi * 3 + 2]);
        }
    }

    float4* dst = (float4*)(out + ((size_t)(b0 + b) * 40000 + n0 + vl0) * 3);
    dst[0] = make_float4(o[0], o[1], o[2],  o[3]);
    dst[1] = make_float4(o[4], o[5], o[6],  o[7]);
    dst[2] = make_float4(o[8], o[9], o[10], o[11]);
}

// ---------------- Kernel C: skeleton partials + fused final reduction -----------
// grid (30, 8), block (64, 4); last-arriving block per row finalizes.
__global__ __launch_bounds__(256) void k_skel_part(
    const int* __restrict__ joint_idx, const int* __restrict__ add_idx,
    float* __restrict__ out)
{
    int j = blockIdx.x, ch = blockIdx.y;
    const int* row = (j < 23) ? (joint_idx + j * 128) : (add_idx + (j - 23) * 128);

    __shared__ int vs[16];
    __shared__ int ticket;
    int tid = threadIdx.y * 64 + threadIdx.x;
    if (tid < 16) vs[tid] = row[ch * 16 + tid];
    __syncthreads();

    int b = threadIdx.x, q = threadIdx.y;
    float mn0 = 3.4e38f, mn1 = 3.4e38f, mn2 = 3.4e38f;
    float mx0 = -3.4e38f, mx1 = -3.4e38f, mx2 = -3.4e38f;
    #pragma unroll
    for (int i = 0; i < 4; i++) {
        int v = vs[q * 4 + i];
        const float* p = out + ((size_t)b * 40000 + v) * 3;
        float x = p[0], y = p[1], z = p[2];
        mn0 = fminf(mn0, x); mx0 = fmaxf(mx0, x);
        mn1 = fminf(mn1, y); mx1 = fmaxf(mx1, y);
        mn2 = fminf(mn2, z); mx2 = fmaxf(mx2, z);
    }
    __shared__ float red[4][64][6];
    red[q][b][0] = mn0; red[q][b][1] = mn1; red[q][b][2] = mn2;
    red[q][b][3] = mx0; red[q][b][4] = mx1; red[q][b][5] = mx2;
    __syncthreads();
    if (q == 0) {
        #pragma unroll
        for (int c = 1; c < 4; c++) {
            mn0 = fminf(mn0, red[c][b][0]); mn1 = fminf(mn1, red[c][b][1]); mn2 = fminf(mn2, red[c][b][2]);
            mx0 = fmaxf(mx0, red[c][b][3]); mx1 = fmaxf(mx1, red[c][b][4]); mx2 = fmaxf(mx2, red[c][b][5]);
        }
        float* dst = g_spart + ((size_t)(j * 8 + ch) * 64 + b) * 6;
        dst[0] = mn0; dst[1] = mn1; dst[2] = mn2;
        dst[3] = mx0; dst[4] = mx1; dst[5] = mx2;
    }

    // threadfence-reduction handoff: last block of the 8 chunks finalizes row j
    __threadfence();
    __syncthreads();
    if (tid == 0) ticket = atomicAdd(&g_cnt[j], 1);
    __syncthreads();
    if (ticket == 7) {
        __threadfence();
        if (q == 0) {
            int orow = (j < 23) ? (1 + j) : (24 + (j - 23));
            float fn0 = 3.4e38f, fn1 = 3.4e38f, fn2 = 3.4e38f;
            float fx0 = -3.4e38f, fx1 = -3.4e38f, fx2 = -3.4e38f;
            #pragma unroll
            for (int c = 0; c < 8; c++) {
                const float* s = g_spart + ((size_t)(j * 8 + c) * 64 + b) * 6;
                fn0 = fminf(fn0, s[0]); fn1 = fminf(fn1, s[1]); fn2 = fminf(fn2, s[2]);
                fx0 = fmaxf(fx0, s[3]); fx1 = fmaxf(fx1, s[4]); fx2 = fmaxf(fx2, s[5]);
            }
            float* s = out + SKEL_OFF + ((size_t)b * 31 + orow) * 3;
            s[0] = 0.5f * (fn0 + fx0);
            s[1] = 0.5f * (fn1 + fx1);
            s[2] = 0.5f * (fn2 + fx2);
            if (j == 0) {
                float* z0 = out + SKEL_OFF + (size_t)b * 31 * 3;
                z0[0] = 0.f; z0[1] = 0.f; z0[2] = 0.f;
            }
        }
        if (tid == 0) atomicExch(&g_cnt[j], 0);   // reset for next graph replay
    }
}

// ---------------- launch ----------------
extern "C" void kernel_launch(void* const* d_in, const int* in_sizes, int n_in,
                              void* d_out, int out_size)
{
    const float* beta      = (const float*)d_in[0];
    const float* pose      = (const float*)d_in[1];
    const float* trans     = (const float*)d_in[2];
    const float* sd        = (const float*)d_in[3];
    const float* vt        = (const float*)d_in[4];
    const float* wts       = (const float*)d_in[5];
    const int*   joint_idx = (const int*)d_in[8];
    const int*   add_idx   = (const int*)d_in[9];
    float* out = (float*)d_out;

    cudaFuncSetAttribute(k_joint_gather, cudaFuncAttributeMaxDynamicSharedMemorySize, 64000);
    cudaFuncSetAttribute(k_main,         cudaFuncAttributeMaxDynamicSharedMemorySize, SM_TOT * 4);

    k_joint_gather<<<dim3(23, 4), dim3(32, 8), 64000>>>(beta, sd, vt, joint_idx);
    k_chain<<<64, 32>>>(pose);
    k_main<<<dim3(1250, 2), dim3(32, 8), SM_TOT * 4>>>(beta, trans, sd, vt, wts, out);
    k_skel_part<<<dim3(30, 8), dim3(64, 4)>>>(joint_idx, add_idx, out);
}